// round 8
// baseline (speedup 1.0000x reference)
#include <cuda_runtime.h>
#include <cuda_bf16.h>
#include <cstdint>

// Problem constants
#define BB 4
#define SS 2048
#define EE 1024
#define HH 16
#define DD 64
#define MTOT (BB * SS)   // 8192

// ---------------------------------------------------------------------------
// Scratch
// ---------------------------------------------------------------------------
__device__ float g_Q[BB * HH * SS * DD];
__device__ float g_K[BB * HH * SS * DD];
__device__ float g_V[BB * HH * SS * DD];
__device__ float g_O[BB * SS * EE];

__device__ __forceinline__ float to_tf32(float x) {
    uint32_t u;
    asm("cvt.rna.tf32.f32 %0, %1;" : "=r"(u) : "f"(x));
    return __uint_as_float(u);
}
__device__ __forceinline__ uint32_t tf32_bits(float x) {
    uint32_t u;
    asm("cvt.rna.tf32.f32 %0, %1;" : "=r"(u) : "f"(x));
    return u;
}

// mma.sync m16n8k8 tf32: D += A(16x8 row) * B(8x8 col)
__device__ __forceinline__ void mma16n8k8(float d[4], const uint32_t a[4],
                                          uint32_t b0, uint32_t b1) {
    asm volatile(
        "mma.sync.aligned.m16n8k8.row.col.f32.tf32.tf32.f32 "
        "{%0,%1,%2,%3}, {%4,%5,%6,%7}, {%8,%9}, {%0,%1,%2,%3};\n"
        : "+f"(d[0]), "+f"(d[1]), "+f"(d[2]), "+f"(d[3])
        : "r"(a[0]), "r"(a[1]), "r"(a[2]), "r"(a[3]), "r"(b0), "r"(b1));
}

// cp.async helpers
__device__ __forceinline__ void cpasync16(uint32_t dst_smem, const void* src) {
    asm volatile("cp.async.ca.shared.global [%0], [%1], 16;\n"
                 :: "r"(dst_smem), "l"(src));
}
__device__ __forceinline__ void cp_commit() {
    asm volatile("cp.async.commit_group;\n");
}
template <int N>
__device__ __forceinline__ void cp_wait() {
    asm volatile("cp.async.wait_group %0;\n" :: "n"(N));
}

// ---------------------------------------------------------------------------
// GEMM + bias (raw mma.m16n8k8 tf32, 3-stage cp.async pipeline)
// Y = X[M,K] @ W[K,N] + b
// CTA 128x128, BK=32, 256 threads = 8 warps (2 M x 4 N), warp tile 64x32
// = 4(M16) x 4(N8) fragments. Smem holds raw f32; cvt.rna at fragment load.
// Pads: GLDA=36 (A-frag banks 4r+c, distinct), GLDB=136 (B-frag banks 8c+r).
// Epilogue: bias + store direct from fragments.
// MODE 0: Y [M,N]; MODE 1: Y [B,H,S,D] head-split (h = global_col/64)
// ---------------------------------------------------------------------------
#define GBM 128
#define GBN 128
#define GBK 32
#define GLDA 36    // 32 + 4 pad (144B rows, 16B aligned)
#define GLDB 136   // 128 + 8 pad (544B rows, 16B aligned)
#define ABUF (GBM * GLDA)   // 4608 floats
#define BBUF (GBK * GLDB)   // 4352 floats
#define GSTAGE 3
#define GSMEM (GSTAGE * (ABUF + BBUF) * 4)   // 107520 bytes

template <int MODE>
__global__ void __launch_bounds__(256, 2) gemm_bias_k(
    const float* __restrict__ X, const float* __restrict__ W,
    const float* __restrict__ bias, float* __restrict__ Y)
{
    extern __shared__ float sm[];

    const int tid = threadIdx.x;
    const int lane = tid & 31;
    const int wid = tid >> 5;
    const int wm = wid >> 2;                // 0..1 -> M offset wm*64
    const int wn = wid & 3;                 // 0..3 -> N offset wn*32
    const int r = lane >> 2;                // 0..7
    const int c = lane & 3;                 // 0..3
    const int m0 = blockIdx.y * GBM;
    const int n0 = blockIdx.x * GBN;

    const uint32_t smem_u32 = (uint32_t)__cvta_generic_to_shared(sm);

    // issue one stage's cp.async loads (A: 128x32, B: 32x128) into buffer `buf`
    auto stage_issue = [&](int kb, int buf) {
        uint32_t abase = smem_u32 + (uint32_t)(buf * (ABUF + BBUF)) * 4u;
        uint32_t bbase = abase + (uint32_t)ABUF * 4u;
#pragma unroll
        for (int it = 0; it < 4; it++) {            // A: 1024 chunks of 16B
            int idx = tid + it * 256;
            int rr = idx >> 3, cc = (idx & 7) * 4;
            cpasync16(abase + (uint32_t)(rr * GLDA + cc) * 4u,
                      &X[(size_t)(m0 + rr) * EE + kb + cc]);
        }
#pragma unroll
        for (int it = 0; it < 4; it++) {            // B: 1024 chunks of 16B
            int idx = tid + it * 256;
            int rr = idx >> 5, cc = (idx & 31) * 4;
            cpasync16(bbase + (uint32_t)(rr * GLDB + cc) * 4u,
                      &W[(size_t)(kb + rr) * EE + n0 + cc]);
        }
    };

    float acc[4][4][4];
#pragma unroll
    for (int mf = 0; mf < 4; mf++)
#pragma unroll
        for (int nf = 0; nf < 4; nf++)
#pragma unroll
            for (int e = 0; e < 4; e++) acc[mf][nf][e] = 0.0f;

    // prologue: stages 0 and 1 in flight
    stage_issue(0, 0);
    cp_commit();
    stage_issue(GBK, 1);
    cp_commit();

    const int NS = EE / GBK;  // 32
    for (int s = 0; s < NS; s++) {
        cp_wait<1>();          // stage s complete
        __syncthreads();       // visible to all; buffer (s+2)%3 free
        if (s + 2 < NS) stage_issue((s + 2) * GBK, (s + 2) % 3);
        cp_commit();           // always commit (empty groups are fine)

        const float* As = sm + (size_t)(s % 3) * (ABUF + BBUF);
        const float* Bs = As + ABUF;

#pragma unroll
        for (int ks = 0; ks < GBK; ks += 8) {
            uint32_t a[4][4];
#pragma unroll
            for (int mf = 0; mf < 4; mf++) {
                const float* Ab = &As[(wm * 64 + mf * 16) * GLDA + ks];
                a[mf][0] = tf32_bits(Ab[r * GLDA + c]);
                a[mf][1] = tf32_bits(Ab[(r + 8) * GLDA + c]);
                a[mf][2] = tf32_bits(Ab[r * GLDA + c + 4]);
                a[mf][3] = tf32_bits(Ab[(r + 8) * GLDA + c + 4]);
            }
#pragma unroll
            for (int nf = 0; nf < 4; nf++) {
                const float* Bb = &Bs[ks * GLDB + wn * 32 + nf * 8 + r];
                uint32_t b0 = tf32_bits(Bb[c * GLDB]);
                uint32_t b1 = tf32_bits(Bb[(c + 4) * GLDB]);
#pragma unroll
                for (int mf = 0; mf < 4; mf++)
                    mma16n8k8(acc[mf][nf], a[mf], b0, b1);
            }
        }
        __syncthreads();       // compute done before buffer reuse next iter
    }

    // ---- epilogue: bias + store straight from fragments
#pragma unroll
    for (int mf = 0; mf < 4; mf++) {
        int m_lo = m0 + wm * 64 + mf * 16 + r;
        int m_hi = m_lo + 8;
#pragma unroll
        for (int nf = 0; nf < 4; nf++) {
            int nl = wn * 32 + nf * 8 + 2 * c;
            float2 bv = *reinterpret_cast<const float2*>(&bias[n0 + nl]);
            float2 vlo = make_float2(acc[mf][nf][0] + bv.x, acc[mf][nf][1] + bv.y);
            float2 vhi = make_float2(acc[mf][nf][2] + bv.x, acc[mf][nf][3] + bv.y);
            if (MODE == 0) {
                *reinterpret_cast<float2*>(&Y[(size_t)m_lo * EE + n0 + nl]) = vlo;
                *reinterpret_cast<float2*>(&Y[(size_t)m_hi * EE + n0 + nl]) = vhi;
            } else {
                int col = n0 + nl;
                int h = col >> 6, d = col & 63;
                int b_lo = m_lo >> 11, s_lo = m_lo & 2047;
                int b_hi = m_hi >> 11, s_hi = m_hi & 2047;
                *reinterpret_cast<float2*>(
                    &Y[(((size_t)(b_lo * HH + h) * SS + s_lo) * DD) + d]) = vlo;
                *reinterpret_cast<float2*>(
                    &Y[(((size_t)(b_hi * HH + h) * SS + s_hi) * DD) + d]) = vhi;
            }
        }
    }
}

// ---------------------------------------------------------------------------
// Flash attention: 256 threads, Q-tile 128x64, register-resident S/O via
// mma.m16n8k8 tf32. K/V in raw f32, 3-buffer cp.async ring; cvt.rna at
// fragment load. 2 CTAs/SM.
// ---------------------------------------------------------------------------
#define AKLD 68                  // 64 + 4 pad (272B rows, 16B aligned)
#define AVLD 72                  // 64 + 8 pad (288B rows, 16B aligned)
#define KBUFF (64 * AKLD)        // 4352 floats
#define VBUFF (64 * AVLD)        // 4608 floats
#define ASMEM ((3 * KBUFF + 3 * VBUFF) * 4)   // 107520 bytes

__global__ void __launch_bounds__(256, 2) attn_k(
    const float* __restrict__ Qh, const float* __restrict__ Kh,
    const float* __restrict__ Vh, float* __restrict__ O)
{
    extern __shared__ float sm[];

    const int tid = threadIdx.x;
    const int lane = tid & 31;
    const int w = tid >> 5;
    const int r = lane >> 2;
    const int c = lane & 3;
    const int qi = blockIdx.x;
    const int bh = blockIdx.y;
    const size_t base = (size_t)bh * SS * DD;
    const int q0 = qi * 128;
    const int rw = q0 + w * 16;

    const uint32_t smem_u32 = (uint32_t)__cvta_generic_to_shared(sm);

    // issue K+V tile j into ring buffer `buf`
    auto kv_issue = [&](int j, int buf) {
        const float* Kg = Kh + base + (size_t)j * 64 * DD;
        const float* Vg = Vh + base + (size_t)j * 64 * DD;
        uint32_t kbase = smem_u32 + (uint32_t)(buf * KBUFF) * 4u;
        uint32_t vbase = smem_u32 + (uint32_t)(3 * KBUFF + buf * VBUFF) * 4u;
#pragma unroll
        for (int it = 0; it < 4; it++) {          // 1024 chunks each
            int idx = tid + it * 256;
            int row = idx >> 4, c4 = (idx & 15) * 4;
            cpasync16(kbase + (uint32_t)(row * AKLD + c4) * 4u, &Kg[row * DD + c4]);
            cpasync16(vbase + (uint32_t)(row * AVLD + c4) * 4u, &Vg[row * DD + c4]);
        }
    };

    // ---- stage Q (128x64) into smem scratch (overlaps K ring, used pre-loop)
    {
        const float* Qg = Qh + base + (size_t)q0 * DD;
#pragma unroll
        for (int it = 0; it < 8; it++) {
            int g = it * 256 + tid;
            int row = g >> 4, c4 = (g & 15) * 4;
            float4 v = *reinterpret_cast<const float4*>(&Qg[row * DD + c4]);
            float* d = &sm[row * AKLD + c4];
            d[0] = v.x; d[1] = v.y; d[2] = v.z; d[3] = v.w;
        }
    }
    __syncthreads();

    // ---- build Q A-fragments (scaled + tf32)
    uint32_t Qa[8][4];
    {
        const float scale = 0.125f;   // 1/sqrt(64)
#pragma unroll
        for (int k = 0; k < 8; k++) {
            int kc = k * 8;
            Qa[k][0] = tf32_bits(sm[(w*16 + r)     * AKLD + kc + c]     * scale);
            Qa[k][1] = tf32_bits(sm[(w*16 + r + 8) * AKLD + kc + c]     * scale);
            Qa[k][2] = tf32_bits(sm[(w*16 + r)     * AKLD + kc + c + 4] * scale);
            Qa[k][3] = tf32_bits(sm[(w*16 + r + 8) * AKLD + kc + c + 4] * scale);
        }
    }
    __syncthreads();   // Q reads done before cp.async overwrites K ring

    const int jmax = 2 * qi + 1;

    // prologue: tiles 0 and 1 in flight
    kv_issue(0, 0);
    cp_commit();
    if (1 <= jmax) kv_issue(1, 1);
    cp_commit();

    float Oa[8][4];
#pragma unroll
    for (int dn = 0; dn < 8; dn++)
#pragma unroll
        for (int e = 0; e < 4; e++) Oa[dn][e] = 0.0f;
    float m0 = -1e30f, m1 = -1e30f, l0 = 0.0f, l1 = 0.0f;

    const int src0 = (lane & ~3) | (c >> 1);
    const int src1 = src0 + 2;
    const bool odd = (c & 1);

    for (int j = 0; j <= jmax; j++) {
        cp_wait<1>();          // tile j landed
        __syncthreads();
        if (j + 2 <= jmax) kv_issue(j + 2, (j + 2) % 3);
        cp_commit();

        const float* Ks = sm + (size_t)(j % 3) * KBUFF;
        const float* Vs = sm + (size_t)(3 * KBUFF) + (size_t)(j % 3) * VBUFF;

        const bool active = (j * 64) <= (rw + 15);
        if (active) {
            // ---- S = Q @ K^T (cvt at load)
            float Sa[8][4];
#pragma unroll
            for (int nt = 0; nt < 8; nt++)
#pragma unroll
                for (int e = 0; e < 4; e++) Sa[nt][e] = 0.0f;
#pragma unroll
            for (int k = 0; k < 8; k++) {
#pragma unroll
                for (int nt = 0; nt < 8; nt++) {
                    uint32_t b0 = tf32_bits(Ks[(nt*8 + r) * AKLD + k*8 + c]);
                    uint32_t b1 = tf32_bits(Ks[(nt*8 + r) * AKLD + k*8 + c + 4]);
                    mma16n8k8(Sa[nt], Qa[k], b0, b1);
                }
            }

            if (j * 64 + 63 > rw) {
#pragma unroll
                for (int nt = 0; nt < 8; nt++) {
                    int colb = j * 64 + nt * 8 + 2 * c;
                    if (colb     > rw + r)     Sa[nt][0] = -1e30f;
                    if (colb + 1 > rw + r)     Sa[nt][1] = -1e30f;
                    if (colb     > rw + r + 8) Sa[nt][2] = -1e30f;
                    if (colb + 1 > rw + r + 8) Sa[nt][3] = -1e30f;
                }
            }

            // ---- online softmax
            float t0 = -1e30f, t1 = -1e30f;
#pragma unroll
            for (int nt = 0; nt < 8; nt++) {
                t0 = fmaxf(t0, fmaxf(Sa[nt][0], Sa[nt][1]));
                t1 = fmaxf(t1, fmaxf(Sa[nt][2], Sa[nt][3]));
            }
            t0 = fmaxf(t0, __shfl_xor_sync(0xffffffffu, t0, 1));
            t0 = fmaxf(t0, __shfl_xor_sync(0xffffffffu, t0, 2));
            t1 = fmaxf(t1, __shfl_xor_sync(0xffffffffu, t1, 1));
            t1 = fmaxf(t1, __shfl_xor_sync(0xffffffffu, t1, 2));
            float mn0 = fmaxf(m0, t0), mn1 = fmaxf(m1, t1);
            float cr0 = __expf(m0 - mn0), cr1 = __expf(m1 - mn1);
            m0 = mn0; m1 = mn1;

            float rs0 = 0.0f, rs1 = 0.0f;
#pragma unroll
            for (int nt = 0; nt < 8; nt++) {
                Sa[nt][0] = __expf(Sa[nt][0] - mn0);
                Sa[nt][1] = __expf(Sa[nt][1] - mn0);
                Sa[nt][2] = __expf(Sa[nt][2] - mn1);
                Sa[nt][3] = __expf(Sa[nt][3] - mn1);
                rs0 += Sa[nt][0] + Sa[nt][1];
                rs1 += Sa[nt][2] + Sa[nt][3];
            }
            rs0 += __shfl_xor_sync(0xffffffffu, rs0, 1);
            rs0 += __shfl_xor_sync(0xffffffffu, rs0, 2);
            rs1 += __shfl_xor_sync(0xffffffffu, rs1, 1);
            rs1 += __shfl_xor_sync(0xffffffffu, rs1, 2);
            l0 = l0 * cr0 + rs0;
            l1 = l1 * cr1 + rs1;

#pragma unroll
            for (int dn = 0; dn < 8; dn++) {
                Oa[dn][0] *= cr0; Oa[dn][1] *= cr0;
                Oa[dn][2] *= cr1; Oa[dn][3] *= cr1;
            }

            // ---- O += P @ V (P: C-layout -> A-layout via quad shuffles)
#pragma unroll
            for (int nt = 0; nt < 8; nt++) {
                float p0 = to_tf32(Sa[nt][0]);
                float p1 = to_tf32(Sa[nt][1]);
                float p2 = to_tf32(Sa[nt][2]);
                float p3 = to_tf32(Sa[nt][3]);
                float x0 = __shfl_sync(0xffffffffu, p0, src0);
                float x1 = __shfl_sync(0xffffffffu, p1, src0);
                float y0 = __shfl_sync(0xffffffffu, p0, src1);
                float y1 = __shfl_sync(0xffffffffu, p1, src1);
                float z0 = __shfl_sync(0xffffffffu, p2, src0);
                float z1 = __shfl_sync(0xffffffffu, p3, src0);
                float u0 = __shfl_sync(0xffffffffu, p2, src1);
                float u1 = __shfl_sync(0xffffffffu, p3, src1);
                uint32_t A[4];
                A[0] = __float_as_uint(odd ? x1 : x0);
                A[1] = __float_as_uint(odd ? z1 : z0);
                A[2] = __float_as_uint(odd ? y1 : y0);
                A[3] = __float_as_uint(odd ? u1 : u0);
#pragma unroll
                for (int dn = 0; dn < 8; dn++) {
                    uint32_t b0 = tf32_bits(Vs[(nt*8 + c)     * AVLD + dn*8 + r]);
                    uint32_t b1 = tf32_bits(Vs[(nt*8 + c + 4) * AVLD + dn*8 + r]);
                    mma16n8k8(Oa[dn], A, b0, b1);
                }
            }
        }
        __syncthreads();   // compute done before ring slot reuse
    }

    // ---- epilogue: normalize + write O in [B,S,E] layout
    const float inv0 = 1.0f / l0;
    const float inv1 = 1.0f / l1;
    const int b = bh >> 4, h = bh & 15;
    const int row0 = rw + r, row1 = rw + r + 8;
    float* O0 = O + ((size_t)b * SS + row0) * EE + h * 64;
    float* O1 = O + ((size_t)b * SS + row1) * EE + h * 64;
#pragma unroll
    for (int dn = 0; dn < 8; dn++) {
        int col = dn * 8 + 2 * c;
        float2 v0 = make_float2(Oa[dn][0] * inv0, Oa[dn][1] * inv0);
        float2 v1 = make_float2(Oa[dn][2] * inv1, Oa[dn][3] * inv1);
        *reinterpret_cast<float2*>(&O0[col]) = v0;
        *reinterpret_cast<float2*>(&O1[col]) = v1;
    }
}

// ---------------------------------------------------------------------------
// Launch
// ---------------------------------------------------------------------------
extern "C" void kernel_launch(void* const* d_in, const int* in_sizes, int n_in,
                              void* d_out, int out_size)
{
    const float* q   = (const float*)d_in[0];
    const float* k   = (const float*)d_in[1];
    const float* v   = (const float*)d_in[2];
    const float* w_q = (const float*)d_in[3];
    const float* b_q = (const float*)d_in[4];
    const float* w_k = (const float*)d_in[5];
    const float* b_k = (const float*)d_in[6];
    const float* w_v = (const float*)d_in[7];
    const float* b_v = (const float*)d_in[8];
    const float* w_o = (const float*)d_in[9];
    const float* b_o = (const float*)d_in[10];
    float* out = (float*)d_out;

    cudaFuncSetAttribute(gemm_bias_k<0>,
                         cudaFuncAttributeMaxDynamicSharedMemorySize, GSMEM);
    cudaFuncSetAttribute(gemm_bias_k<1>,
                         cudaFuncAttributeMaxDynamicSharedMemorySize, GSMEM);
    cudaFuncSetAttribute(attn_k,
                         cudaFuncAttributeMaxDynamicSharedMemorySize, ASMEM);

    float* gQ;  cudaGetSymbolAddress((void**)&gQ, g_Q);
    float* gK;  cudaGetSymbolAddress((void**)&gK, g_K);
    float* gV;  cudaGetSymbolAddress((void**)&gV, g_V);
    float* gO;  cudaGetSymbolAddress((void**)&gO, g_O);

    dim3 ggrid(EE / GBN, MTOT / GBM);  // (8, 64)

    gemm_bias_k<1><<<ggrid, 256, GSMEM>>>(q, w_q, b_q, gQ);
    gemm_bias_k<1><<<ggrid, 256, GSMEM>>>(k, w_k, b_k, gK);
    gemm_bias_k<1><<<ggrid, 256, GSMEM>>>(v, w_v, b_v, gV);

    attn_k<<<dim3(SS / 128, BB * HH), 256, ASMEM>>>(gQ, gK, gV, gO);

    gemm_bias_k<0><<<ggrid, 256, GSMEM>>>(gO, w_o, b_o, out);
}